// round 2
// baseline (speedup 1.0000x reference)
#include <cuda_runtime.h>
#include <math.h>

#define Nn 20000
#define Cc 256
#define Ee 100000
#define RC 4      // R*CH
#define Mrows (RC * Nn)   // 80000

// Scratch (device globals: allocation-free rule)
__device__ float g_xl[RC * Nn * Cc];     // x @ lin_W + lin_b
__device__ float g_sums[RC * Nn * Cc];   // scatter-add accumulator
__device__ float g_cnt[Nn];
__device__ float g_inv[Nn];

// ---------------------------------------------------------------------------
__global__ void zero_kernel() {
    int idx = blockIdx.x * blockDim.x + threadIdx.x;   // 5.12M threads == exactly (RC*Nn*Cc)/4
    ((float4*)g_sums)[idx] = make_float4(0.f, 0.f, 0.f, 0.f);
    if (idx < Nn) g_cnt[idx] = 0.f;
}

__global__ void count_kernel(const int* __restrict__ ei) {
    int e = blockIdx.x * blockDim.x + threadIdx.x;
    if (e < Ee) atomicAdd(&g_cnt[ei[Ee + e]], 1.0f);
}

__global__ void inv_kernel() {
    int n = blockIdx.x * blockDim.x + threadIdx.x;
    if (n < Nn) g_inv[n] = 1.0f / fmaxf(g_cnt[n], 1.0f);
}

// ---------------------------------------------------------------------------
// SGEMM: g_xl = x(80000x256) @ lin_W(256x256) + lin_b   (128x128x8 tiling)
__global__ __launch_bounds__(256, 2)
void sgemm_xl_kernel(const float* __restrict__ A, const float* __restrict__ B,
                     const float* __restrict__ bias) {
    __shared__ float As[8][132];
    __shared__ float Bs[8][128];
    int tid = threadIdx.x;
    int tx = tid & 15, ty = tid >> 4;
    int br = blockIdx.y, bc = blockIdx.x;
    int aRow = tid >> 1, aCol = (tid & 1) * 4;
    int bRow = tid >> 5, bCol = (tid & 31) * 4;
    const float* Ap = A + (size_t)(br * 128 + aRow) * 256 + aCol;
    const float* Bp = B + (size_t)bRow * 256 + bc * 128 + bCol;
    float acc[8][8] = {};
    for (int k0 = 0; k0 < 256; k0 += 8) {
        float4 av = *(const float4*)(Ap + k0);
        float4 bv = *(const float4*)(Bp + (size_t)k0 * 256);
        As[aCol + 0][aRow] = av.x; As[aCol + 1][aRow] = av.y;
        As[aCol + 2][aRow] = av.z; As[aCol + 3][aRow] = av.w;
        *(float4*)&Bs[bRow][bCol] = bv;
        __syncthreads();
#pragma unroll
        for (int kk = 0; kk < 8; kk++) {
            float a[8], b[8];
            *(float4*)&a[0] = *(const float4*)&As[kk][ty * 8];
            *(float4*)&a[4] = *(const float4*)&As[kk][ty * 8 + 4];
            *(float4*)&b[0] = *(const float4*)&Bs[kk][tx * 8];
            *(float4*)&b[4] = *(const float4*)&Bs[kk][tx * 8 + 4];
#pragma unroll
            for (int i = 0; i < 8; i++)
#pragma unroll
                for (int j = 0; j < 8; j++)
                    acc[i][j] = fmaf(a[i], b[j], acc[i][j]);
        }
        __syncthreads();
    }
    int col = bc * 128 + tx * 8;
#pragma unroll
    for (int i = 0; i < 8; i++) {
        float* Cp = g_xl + (size_t)(br * 128 + ty * 8 + i) * 256 + col;
        float4 o0 = make_float4(acc[i][0] + bias[col + 0], acc[i][1] + bias[col + 1],
                                acc[i][2] + bias[col + 2], acc[i][3] + bias[col + 3]);
        float4 o1 = make_float4(acc[i][4] + bias[col + 4], acc[i][5] + bias[col + 5],
                                acc[i][6] + bias[col + 6], acc[i][7] + bias[col + 7]);
        *(float4*)Cp = o0;
        *(float4*)(Cp + 4) = o1;
    }
}

// ---------------------------------------------------------------------------
// Message kernel: fused bond-encoder + gather + exact GELU + weight + atomic scatter.
// One block handles 32 edges; thread t owns channel t.
__global__ __launch_bounds__(256)
void msg_kernel(const float* __restrict__ edge_attr,
                const float* __restrict__ edge_weight,
                const float* __restrict__ bond_W,
                const float* __restrict__ bond_b,
                const int* __restrict__ ei) {
    __shared__ float bw_s[16 * 256];
    __shared__ float attrs[32 * 16];
    __shared__ float ews[4 * 32];
    __shared__ int srcs[32], dsts[32];
    int tid = threadIdx.x;
    int e0 = blockIdx.x * 32;
#pragma unroll
    for (int k = 0; k < 16; k++) bw_s[k * 256 + tid] = bond_W[k * 256 + tid];
    for (int idx = tid; idx < 32 * 16; idx += 256) {
        int el = idx >> 4, k = idx & 15;
        attrs[idx] = edge_attr[(size_t)(e0 + el) * 16 + k];
    }
    if (tid < 128) {
        int rc = tid >> 5, j = tid & 31;
        ews[tid] = edge_weight[(size_t)rc * Ee + e0 + j];
    }
    if (tid < 32) {
        srcs[tid] = ei[e0 + tid];
        dsts[tid] = ei[Ee + e0 + tid];
    }
    float bb = bond_b[tid];
    __syncthreads();
    int c = tid;
    for (int el = 0; el < 32; el++) {
        float emb = bb;
#pragma unroll
        for (int k = 0; k < 16; k++)
            emb = fmaf(attrs[el * 16 + k], bw_s[k * 256 + c], emb);
        int s = srcs[el], d = dsts[el];
#pragma unroll
        for (int rc = 0; rc < 4; rc++) {
            float v = g_xl[(size_t)(rc * Nn + s) * Cc + c] + emb;
            float g = 0.5f * v * (1.0f + erff(v * 0.70710678118654752f));
            atomicAdd(&g_sums[(size_t)(rc * Nn + d) * Cc + c], g * ews[rc * 32 + el]);
        }
    }
}

// ---------------------------------------------------------------------------
// Final fused GEMM: out = (g_sums * inv_cnt) @ linl_W + linl_b + x @ linr_W
// Single K=512 loop: first 32 k-tiles from scaled sums/linl_W, next 32 from x/linr_W.
__global__ __launch_bounds__(256, 2)
void final_kernel(const float* __restrict__ x, const float* __restrict__ Wl,
                  const float* __restrict__ bl, const float* __restrict__ Wr,
                  float* __restrict__ out) {
    __shared__ float As[8][132];
    __shared__ float Bs[8][128];
    __shared__ float invr[128];
    int tid = threadIdx.x;
    int tx = tid & 15, ty = tid >> 4;
    int br = blockIdx.y, bc = blockIdx.x;
    int aRow = tid >> 1, aCol = (tid & 1) * 4;
    int bRow = tid >> 5, bCol = (tid & 31) * 4;
    if (tid < 128) invr[tid] = g_inv[(br * 128 + tid) % Nn];
    __syncthreads();
    const float* Ap0 = g_sums + (size_t)(br * 128 + aRow) * 256 + aCol;
    const float* Ap1 = x + (size_t)(br * 128 + aRow) * 256 + aCol;
    float acc[8][8] = {};
    for (int t = 0; t < 64; t++) {
        float4 av, bv;
        if (t < 32) {
            int k0 = t * 8;
            av = *(const float4*)(Ap0 + k0);
            float s = invr[aRow];
            av.x *= s; av.y *= s; av.z *= s; av.w *= s;
            bv = *(const float4*)(Wl + (size_t)(k0 + bRow) * 256 + bc * 128 + bCol);
        } else {
            int k0 = (t - 32) * 8;
            av = *(const float4*)(Ap1 + k0);
            bv = *(const float4*)(Wr + (size_t)(k0 + bRow) * 256 + bc * 128 + bCol);
        }
        As[aCol + 0][aRow] = av.x; As[aCol + 1][aRow] = av.y;
        As[aCol + 2][aRow] = av.z; As[aCol + 3][aRow] = av.w;
        *(float4*)&Bs[bRow][bCol] = bv;
        __syncthreads();
#pragma unroll
        for (int kk = 0; kk < 8; kk++) {
            float a[8], b[8];
            *(float4*)&a[0] = *(const float4*)&As[kk][ty * 8];
            *(float4*)&a[4] = *(const float4*)&As[kk][ty * 8 + 4];
            *(float4*)&b[0] = *(const float4*)&Bs[kk][tx * 8];
            *(float4*)&b[4] = *(const float4*)&Bs[kk][tx * 8 + 4];
#pragma unroll
            for (int i = 0; i < 8; i++)
#pragma unroll
                for (int j = 0; j < 8; j++)
                    acc[i][j] = fmaf(a[i], b[j], acc[i][j]);
        }
        __syncthreads();
    }
    int col = bc * 128 + tx * 8;
#pragma unroll
    for (int i = 0; i < 8; i++) {
        float* Cp = out + (size_t)(br * 128 + ty * 8 + i) * 256 + col;
        float4 o0 = make_float4(acc[i][0] + bl[col + 0], acc[i][1] + bl[col + 1],
                                acc[i][2] + bl[col + 2], acc[i][3] + bl[col + 3]);
        float4 o1 = make_float4(acc[i][4] + bl[col + 4], acc[i][5] + bl[col + 5],
                                acc[i][6] + bl[col + 6], acc[i][7] + bl[col + 7]);
        *(float4*)Cp = o0;
        *(float4*)(Cp + 4) = o1;
    }
}

// ---------------------------------------------------------------------------
extern "C" void kernel_launch(void* const* d_in, const int* in_sizes, int n_in,
                              void* d_out, int out_size) {
    const float* x           = (const float*)d_in[0];
    const float* edge_attr   = (const float*)d_in[1];
    const float* edge_weight = (const float*)d_in[2];
    const float* lin_W       = (const float*)d_in[3];
    const float* lin_b       = (const float*)d_in[4];
    const float* linl_W      = (const float*)d_in[5];
    const float* linl_b      = (const float*)d_in[6];
    const float* linr_W      = (const float*)d_in[7];
    const float* bond_W      = (const float*)d_in[8];
    const float* bond_b      = (const float*)d_in[9];
    const int*   ei          = (const int*)d_in[10];   // jax default x64-disabled -> int32
    float* out = (float*)d_out;

    zero_kernel<<<20000, 256>>>();
    count_kernel<<<(Ee + 255) / 256, 256>>>(ei);
    inv_kernel<<<(Nn + 255) / 256, 256>>>();
    sgemm_xl_kernel<<<dim3(2, 625), 256>>>(x, lin_W, lin_b);
    msg_kernel<<<Ee / 32, 256>>>(edge_attr, edge_weight, bond_W, bond_b, ei);
    final_kernel<<<dim3(2, 625), 256>>>(x, linl_W, linl_b, linr_W, out);
}

// round 6
// speedup vs baseline: 1.1979x; 1.1979x over previous
#include <cuda_runtime.h>
#include <cuda_bf16.h>
#include <math.h>
#include <stdint.h>

#define Nn 20000
#define Cc 256
#define Ee 100000
#define RC 4

// ---------------- device scratch ----------------
__device__ float g_xl[RC * Nn * Cc];
__device__ float g_sums[RC * Nn * Cc];
__device__ float g_cnt[Nn];
__device__ float g_inv[Nn];
// weight images: [kb][h][hi/lo][8192 bf16]; each = 128 n-rows x 64 k-cols, SW128 swizzled
__device__ __nv_bfloat16 g_B1[4 * 2 * 2 * 8192];
__device__ __nv_bfloat16 g_B2[8 * 2 * 2 * 8192];

__device__ __forceinline__ uint32_t smem_u32(const void* p) {
    uint32_t a;
    asm("{ .reg .u64 t; cvta.to.shared.u64 t, %1; cvt.u32.u64 %0, t; }" : "=r"(a) : "l"(p));
    return a;
}
__host__ __device__ __forceinline__ uint32_t SWZ(uint32_t off) { return off ^ ((off >> 3) & 0x70); }

__device__ __forceinline__ void ldsm4(uint32_t& r0, uint32_t& r1, uint32_t& r2, uint32_t& r3,
                                      uint32_t addr) {
    asm volatile("ldmatrix.sync.aligned.m8n8.x4.shared.b16 {%0,%1,%2,%3}, [%4];"
                 : "=r"(r0), "=r"(r1), "=r"(r2), "=r"(r3) : "r"(addr));
}
__device__ __forceinline__ void mma16816(float* c, const uint32_t* a, uint32_t b0, uint32_t b1) {
    asm volatile(
        "mma.sync.aligned.m16n8k16.row.col.f32.bf16.bf16.f32 "
        "{%0,%1,%2,%3}, {%4,%5,%6,%7}, {%8,%9}, {%0,%1,%2,%3};"
        : "+f"(c[0]), "+f"(c[1]), "+f"(c[2]), "+f"(c[3])
        : "r"(a[0]), "r"(a[1]), "r"(a[2]), "r"(a[3]), "r"(b0), "r"(b1));
}

// ---------------- small kernels ----------------
__global__ void zero_kernel() {
    int idx = blockIdx.x * blockDim.x + threadIdx.x;   // 5.12M == (RC*Nn*Cc)/4
    ((float4*)g_sums)[idx] = make_float4(0.f, 0.f, 0.f, 0.f);
    if (idx < Nn) g_cnt[idx] = 0.f;
}
__global__ void count_kernel(const int* __restrict__ ei) {
    int e = blockIdx.x * blockDim.x + threadIdx.x;
    if (e < Ee) atomicAdd(&g_cnt[ei[Ee + e]], 1.0f);
}
__global__ void inv_kernel() {
    int n = blockIdx.x * blockDim.x + threadIdx.x;
    if (n < Nn) g_inv[n] = 1.0f / fmaxf(g_cnt[n], 1.0f);
}

// Pre-split weights into swizzled bf16 hi/lo images (B image = [n][k] = W transposed)
__global__ void prep_weights(const float* __restrict__ lin_W, const float* __restrict__ linl_W,
                             const float* __restrict__ linr_W) {
    int idx = blockIdx.x * blockDim.x + threadIdx.x;
    if (idx >= 3 * 65536) return;
    int m = idx >> 16;
    int kn = idx & 65535;
    int k = kn >> 8, n = kn & 255;
    const float* W = (m == 0) ? lin_W : ((m == 1) ? linl_W : linr_W);
    float v = W[k * 256 + n];
    __nv_bfloat16 hb = __float2bfloat16(v);
    __nv_bfloat16 lb = __float2bfloat16(v - __bfloat162float(hb));
    int h = n >> 7, np = n & 127, kb = k >> 6, kc = k & 63;
    uint32_t elem = SWZ((uint32_t)(np * 128 + kc * 2)) >> 1;
    if (m == 0) {
        size_t base = ((size_t)(kb * 2 + h) * 2) * 8192;
        g_B1[base + elem] = hb;
        g_B1[base + 8192 + elem] = lb;
    } else {
        int kb2 = (m == 1) ? kb : kb + 4;
        size_t base = ((size_t)(kb2 * 2 + h) * 2) * 8192;
        g_B2[base + elem] = hb;
        g_B2[base + 8192 + elem] = lb;
    }
}

// ---------------- split-bf16 mma.sync GEMM ----------------
// mode 0: g_xl = x @ lin_W + lin_b                              (KB=4)
// mode 1: Out = (g_sums*inv) @ linl_W + linl_b + x @ linr_W     (KB=8)
// grid (2, 625): blockIdx.x = N-half, blockIdx.y = 128-row block. 8 warps: 4(M) x 2(N).
__global__ __launch_bounds__(256, 2)
void mm_gemm(const float* __restrict__ X, const float* __restrict__ bias,
             float* __restrict__ Out, int KB, int mode) {
    extern __shared__ __align__(1024) char smem[];
    // AHI 0 (16K), ALO 16384, BHI 32768, BLO 49152, invr 65536
    int tid = threadIdx.x, lane = tid & 31, wid = tid >> 5;
    int warp_m = wid & 3, warp_n = wid >> 2;
    int h = blockIdx.x, br = blockIdx.y;
    float* invr = (float*)(smem + 65536);
    if (mode == 1 && tid < 128) invr[tid] = g_inv[(br * 128 + tid) % Nn];
    __syncthreads();

    const __nv_bfloat16* Bimg = mode ? g_B2 : g_B1;
    float* dst = mode ? Out : g_xl;
    uint32_t sA = smem_u32(smem), sB = sA + 32768;

    float acc[2][8][4] = {};

    for (int kb = 0; kb < KB; kb++) {
        const float* src;
        int cb;
        bool sc;
        if (mode == 1 && kb < 4) { src = g_sums; cb = kb * 64; sc = true; }
        else { src = X; cb = (mode == 1 ? (kb - 4) * 64 : kb * 64); sc = false; }
        // A tile: 128 rows x 64 fp32 -> bf16 hi/lo, SW128
        for (int i = tid; i < 2048; i += 256) {
            int row = i >> 4, q = i & 15;
            float4 v = *(const float4*)(src + (size_t)(br * 128 + row) * 256 + cb + q * 4);
            if (sc) { float s = invr[row]; v.x *= s; v.y *= s; v.z *= s; v.w *= s; }
            float fv[4] = {v.x, v.y, v.z, v.w};
            uint32_t hp[2], lp[2];
#pragma unroll
            for (int p = 0; p < 2; p++) {
                __nv_bfloat16 h0 = __float2bfloat16(fv[2 * p]);
                __nv_bfloat16 h1 = __float2bfloat16(fv[2 * p + 1]);
                __nv_bfloat16 l0 = __float2bfloat16(fv[2 * p] - __bfloat162float(h0));
                __nv_bfloat16 l1 = __float2bfloat16(fv[2 * p + 1] - __bfloat162float(h1));
                unsigned short uh0 = *(unsigned short*)&h0, uh1 = *(unsigned short*)&h1;
                unsigned short ul0 = *(unsigned short*)&l0, ul1 = *(unsigned short*)&l1;
                hp[p] = (uint32_t)uh0 | ((uint32_t)uh1 << 16);
                lp[p] = (uint32_t)ul0 | ((uint32_t)ul1 << 16);
            }
            uint32_t sw = SWZ((uint32_t)(row * 128 + q * 8));
            *(uint2*)(smem + sw) = make_uint2(hp[0], hp[1]);
            *(uint2*)(smem + 16384 + sw) = make_uint2(lp[0], lp[1]);
        }
        // B: copy hi+lo images (32KB contiguous) for this half
        {
            const uint4* bsrc = (const uint4*)(Bimg + ((size_t)(kb * 2 + h) * 2) * 8192);
            uint4* bd = (uint4*)(smem + 32768);
            for (int i = tid; i < 2048; i += 256) bd[i] = bsrc[i];
        }
        __syncthreads();

#pragma unroll
        for (int ks = 0; ks < 4; ks++) {
            int koff = ks * 32 + ((lane >> 4) * 16);   // bytes: lanes>=16 read k+8 elems
            uint32_t ahi[2][4], alo[2][4];
#pragma unroll
            for (int mf = 0; mf < 2; mf++) {
                int row = warp_m * 32 + mf * 16 + (lane & 15);
                uint32_t off = SWZ((uint32_t)(row * 128 + koff));
                ldsm4(ahi[mf][0], ahi[mf][1], ahi[mf][2], ahi[mf][3], sA + off);
                ldsm4(alo[mf][0], alo[mf][1], alo[mf][2], alo[mf][3], sA + 16384 + off);
            }
#pragma unroll
            for (int np = 0; np < 4; np++) {
                int n = warp_n * 64 + np * 16 + (lane & 15);
                uint32_t off = SWZ((uint32_t)(n * 128 + koff));
                uint32_t bh0, bh1, bh2, bh3, bl0, bl1, bl2, bl3;
                ldsm4(bh0, bh1, bh2, bh3, sB + off);
                ldsm4(bl0, bl1, bl2, bl3, sB + 16384 + off);
#pragma unroll
                for (int mf = 0; mf < 2; mf++) {
                    float* c0 = acc[mf][np * 2];
                    float* c1 = acc[mf][np * 2 + 1];
                    mma16816(c0, ahi[mf], bh0, bh2);
                    mma16816(c0, ahi[mf], bl0, bl2);
                    mma16816(c0, alo[mf], bh0, bh2);
                    mma16816(c1, ahi[mf], bh1, bh3);
                    mma16816(c1, ahi[mf], bl1, bl3);
                    mma16816(c1, alo[mf], bh1, bh3);
                }
            }
        }
        __syncthreads();
    }

    // epilogue: c-frag -> gmem (+bias)
    int gid = lane >> 2, tig = lane & 3;
#pragma unroll
    for (int mf = 0; mf < 2; mf++) {
#pragma unroll
        for (int nf = 0; nf < 8; nf++) {
            int col = h * 128 + warp_n * 64 + nf * 8 + tig * 2;
            float2 bv = *(const float2*)(bias + col);
            int row0 = br * 128 + warp_m * 32 + mf * 16 + gid;
            float* c = acc[mf][nf];
            *(float2*)(dst + (size_t)row0 * 256 + col) = make_float2(c[0] + bv.x, c[1] + bv.y);
            *(float2*)(dst + (size_t)(row0 + 8) * 256 + col) = make_float2(c[2] + bv.x, c[3] + bv.y);
        }
    }
}

// ---------------- message kernel (unchanged) ----------------
__global__ __launch_bounds__(256)
void msg_kernel(const float* __restrict__ edge_attr,
                const float* __restrict__ edge_weight,
                const float* __restrict__ bond_W,
                const float* __restrict__ bond_b,
                const int* __restrict__ ei) {
    __shared__ float bw_s[16 * 256];
    __shared__ float attrs[32 * 16];
    __shared__ float ews[4 * 32];
    __shared__ int srcs[32], dsts[32];
    int tid = threadIdx.x;
    int e0 = blockIdx.x * 32;
#pragma unroll
    for (int k = 0; k < 16; k++) bw_s[k * 256 + tid] = bond_W[k * 256 + tid];
    for (int idx = tid; idx < 32 * 16; idx += 256) {
        int el = idx >> 4, k = idx & 15;
        attrs[idx] = edge_attr[(size_t)(e0 + el) * 16 + k];
    }
    if (tid < 128) {
        int rc = tid >> 5, j = tid & 31;
        ews[tid] = edge_weight[(size_t)rc * Ee + e0 + j];
    }
    if (tid < 32) {
        srcs[tid] = ei[e0 + tid];
        dsts[tid] = ei[Ee + e0 + tid];
    }
    float bb = bond_b[tid];
    __syncthreads();
    int c = tid;
    for (int el = 0; el < 32; el++) {
        float emb = bb;
#pragma unroll
        for (int k = 0; k < 16; k++)
            emb = fmaf(attrs[el * 16 + k], bw_s[k * 256 + c], emb);
        int s = srcs[el], d = dsts[el];
#pragma unroll
        for (int rc = 0; rc < 4; rc++) {
            float v = g_xl[(size_t)(rc * Nn + s) * Cc + c] + emb;
            float g = 0.5f * v * (1.0f + erff(v * 0.70710678118654752f));
            atomicAdd(&g_sums[(size_t)(rc * Nn + d) * Cc + c], g * ews[rc * 32 + el]);
        }
    }
}

// ---------------------------------------------------------------------------
extern "C" void kernel_launch(void* const* d_in, const int* in_sizes, int n_in,
                              void* d_out, int out_size) {
    const float* x           = (const float*)d_in[0];
    const float* edge_attr   = (const float*)d_in[1];
    const float* edge_weight = (const float*)d_in[2];
    const float* lin_W       = (const float*)d_in[3];
    const float* lin_b       = (const float*)d_in[4];
    const float* linl_W      = (const float*)d_in[5];
    const float* linl_b      = (const float*)d_in[6];
    const float* linr_W      = (const float*)d_in[7];
    const float* bond_W      = (const float*)d_in[8];
    const float* bond_b      = (const float*)d_in[9];
    const int*   ei          = (const int*)d_in[10];
    float* out = (float*)d_out;

    const int SMEM_BYTES = 65536 + 512;
    cudaFuncSetAttribute(mm_gemm, cudaFuncAttributeMaxDynamicSharedMemorySize, SMEM_BYTES);

    prep_weights<<<768, 256>>>(lin_W, linl_W, linr_W);
    zero_kernel<<<20000, 256>>>();
    count_kernel<<<(Ee + 255) / 256, 256>>>(ei);
    inv_kernel<<<(Nn + 255) / 256, 256>>>();
    mm_gemm<<<dim3(2, 625), 256, SMEM_BYTES>>>(x, lin_b, nullptr, 4, 0);
    msg_kernel<<<Ee / 32, 256>>>(edge_attr, edge_weight, bond_W, bond_b, ei);
    mm_gemm<<<dim3(2, 625), 256, SMEM_BYTES>>>(x, linl_b, out, 8, 1);
}

// round 9
// speedup vs baseline: 1.8056x; 1.5073x over previous
#include <cuda_runtime.h>
#include <cuda_bf16.h>
#include <math.h>
#include <stdint.h>

#define Nn 20000
#define Cc 256
#define Ee 100000
#define RC 4

// ---------------- device scratch ----------------
__device__ float g_xl[RC * Nn * Cc];
__device__ float g_sums[RC * Nn * Cc];     // holds scatter-MEAN after msg_sorted
__device__ int   g_cnt[Nn];
__device__ int   g_seg[Nn + 1];
__device__ int   g_cursor[Nn];
__device__ int   g_sorted[Ee];
// weight images: [kb][h][hi/lo][8192 bf16]; each = 128 n-rows x 64 k-cols, SW128 swizzled
__device__ __nv_bfloat16 g_B1[4 * 2 * 2 * 8192];
__device__ __nv_bfloat16 g_B2[8 * 2 * 2 * 8192];

__device__ __forceinline__ uint32_t smem_u32(const void* p) {
    uint32_t a;
    asm("{ .reg .u64 t; cvta.to.shared.u64 t, %1; cvt.u32.u64 %0, t; }" : "=r"(a) : "l"(p));
    return a;
}
__host__ __device__ __forceinline__ uint32_t SWZ(uint32_t off) { return off ^ ((off >> 3) & 0x70); }

__device__ __forceinline__ void ldsm4(uint32_t& r0, uint32_t& r1, uint32_t& r2, uint32_t& r3,
                                      uint32_t addr) {
    asm volatile("ldmatrix.sync.aligned.m8n8.x4.shared.b16 {%0,%1,%2,%3}, [%4];"
                 : "=r"(r0), "=r"(r1), "=r"(r2), "=r"(r3) : "r"(addr));
}
__device__ __forceinline__ void mma16816(float* c, const uint32_t* a, uint32_t b0, uint32_t b1) {
    asm volatile(
        "mma.sync.aligned.m16n8k16.row.col.f32.bf16.bf16.f32 "
        "{%0,%1,%2,%3}, {%4,%5,%6,%7}, {%8,%9}, {%0,%1,%2,%3};"
        : "+f"(c[0]), "+f"(c[1]), "+f"(c[2]), "+f"(c[3])
        : "r"(a[0]), "r"(a[1]), "r"(a[2]), "r"(a[3]), "r"(b0), "r"(b1));
}
__device__ __forceinline__ void cp16(uint32_t dst, const void* src) {
    asm volatile("cp.async.cg.shared.global [%0], [%1], 16;" :: "r"(dst), "l"(src));
}

// ---------------- prep / sort kernels ----------------
__global__ void prep_weights(const float* __restrict__ lin_W, const float* __restrict__ linl_W,
                             const float* __restrict__ linr_W) {
    int idx = blockIdx.x * blockDim.x + threadIdx.x;
    if (idx >= 3 * 65536) return;
    int m = idx >> 16;
    int kn = idx & 65535;
    int k = kn >> 8, n = kn & 255;
    const float* W = (m == 0) ? lin_W : ((m == 1) ? linl_W : linr_W);
    float v = W[k * 256 + n];
    __nv_bfloat16 hb = __float2bfloat16(v);
    __nv_bfloat16 lb = __float2bfloat16(v - __bfloat162float(hb));
    int h = n >> 7, np = n & 127, kb = k >> 6, kc = k & 63;
    uint32_t elem = SWZ((uint32_t)(np * 128 + kc * 2)) >> 1;
    if (m == 0) {
        size_t base = ((size_t)(kb * 2 + h) * 2) * 8192;
        g_B1[base + elem] = hb;
        g_B1[base + 8192 + elem] = lb;
    } else {
        int kb2 = (m == 1) ? kb : kb + 4;
        size_t base = ((size_t)(kb2 * 2 + h) * 2) * 8192;
        g_B2[base + elem] = hb;
        g_B2[base + 8192 + elem] = lb;
    }
}

__global__ void zero_cnt() {
    int n = blockIdx.x * blockDim.x + threadIdx.x;
    if (n < Nn) g_cnt[n] = 0;
}
__global__ void count_kernel(const int* __restrict__ ei) {
    int e = blockIdx.x * blockDim.x + threadIdx.x;
    if (e < Ee) atomicAdd(&g_cnt[ei[Ee + e]], 1);
}
// Single-block exclusive scan over g_cnt -> g_seg; also zero cursors.
__global__ void scan_kernel() {
    __shared__ int part[256];
    int t = threadIdx.x;
    const int CH = (Nn + 255) / 256;   // 79
    int base = t * CH;
    int s = 0;
    for (int i = 0; i < CH; i++) {
        int idx = base + i;
        if (idx < Nn) s += g_cnt[idx];
    }
    part[t] = s;
    __syncthreads();
    if (t == 0) {
        int run = 0;
        for (int i = 0; i < 256; i++) { int v = part[i]; part[i] = run; run += v; }
    }
    __syncthreads();
    int run = part[t];
    for (int i = 0; i < CH; i++) {
        int idx = base + i;
        if (idx < Nn) { g_seg[idx] = run; run += g_cnt[idx]; g_cursor[idx] = 0; }
    }
    if (t == 255) g_seg[Nn] = run;
}
__global__ void scatter_kernel(const int* __restrict__ ei) {
    int e = blockIdx.x * blockDim.x + threadIdx.x;
    if (e < Ee) {
        int d = ei[Ee + e];
        int pos = g_seg[d] + atomicAdd(&g_cursor[d], 1);
        g_sorted[pos] = e;
    }
}

// ---------------- split-bf16 mma.sync GEMM ----------------
// mode 0: g_xl = x @ lin_W + lin_b                           (KB=4)
// mode 1: Out = g_sums @ linl_W + linl_b + x @ linr_W        (KB=8; g_sums already mean-scaled)
__global__ __launch_bounds__(256, 2)
void mm_gemm(const float* __restrict__ X, const float* __restrict__ bias,
             float* __restrict__ Out, int KB, int mode) {
    extern __shared__ __align__(1024) char smem[];
    // AHI 0 (16K), ALO 16384, BHI 32768, BLO 49152
    int tid = threadIdx.x, lane = tid & 31, wid = tid >> 5;
    int warp_m = wid & 3, warp_n = wid >> 2;
    int h = blockIdx.x, br = blockIdx.y;

    const __nv_bfloat16* Bimg = mode ? g_B2 : g_B1;
    float* dst = mode ? Out : g_xl;
    uint32_t sA = smem_u32(smem), sB = sA + 32768;

    float acc[2][8][4] = {};

    for (int kb = 0; kb < KB; kb++) {
        const float* src;
        int cb;
        if (mode == 1 && kb < 4) { src = g_sums; cb = kb * 64; }
        else { src = X; cb = (mode == 1 ? (kb - 4) * 64 : kb * 64); }
        // B: async copy hi+lo images (32KB) for this half — overlaps with A conversion
        {
            const uint4* bsrc = (const uint4*)(Bimg + ((size_t)(kb * 2 + h) * 2) * 8192);
            for (int i = tid; i < 2048; i += 256) cp16(sB + i * 16, bsrc + i);
            asm volatile("cp.async.commit_group;");
        }
        // A tile: 128 rows x 64 fp32 -> bf16 hi/lo, SW128
        for (int i = tid; i < 2048; i += 256) {
            int row = i >> 4, q = i & 15;
            float4 v = *(const float4*)(src + (size_t)(br * 128 + row) * 256 + cb + q * 4);
            float fv[4] = {v.x, v.y, v.z, v.w};
            uint32_t hp[2], lp[2];
#pragma unroll
            for (int p = 0; p < 2; p++) {
                __nv_bfloat16 h0 = __float2bfloat16(fv[2 * p]);
                __nv_bfloat16 h1 = __float2bfloat16(fv[2 * p + 1]);
                __nv_bfloat16 l0 = __float2bfloat16(fv[2 * p] - __bfloat162float(h0));
                __nv_bfloat16 l1 = __float2bfloat16(fv[2 * p + 1] - __bfloat162float(h1));
                unsigned short uh0 = *(unsigned short*)&h0, uh1 = *(unsigned short*)&h1;
                unsigned short ul0 = *(unsigned short*)&l0, ul1 = *(unsigned short*)&l1;
                hp[p] = (uint32_t)uh0 | ((uint32_t)uh1 << 16);
                lp[p] = (uint32_t)ul0 | ((uint32_t)ul1 << 16);
            }
            uint32_t sw = SWZ((uint32_t)(row * 128 + q * 8));
            *(uint2*)(smem + sw) = make_uint2(hp[0], hp[1]);
            *(uint2*)(smem + 16384 + sw) = make_uint2(lp[0], lp[1]);
        }
        asm volatile("cp.async.wait_group 0;" ::: "memory");
        __syncthreads();

#pragma unroll
        for (int ks = 0; ks < 4; ks++) {
            int koff = ks * 32 + ((lane >> 4) * 16);   // bytes
            uint32_t ahi[2][4], alo[2][4];
#pragma unroll
            for (int mf = 0; mf < 2; mf++) {
                int row = warp_m * 32 + mf * 16 + (lane & 15);
                uint32_t off = SWZ((uint32_t)(row * 128 + koff));
                ldsm4(ahi[mf][0], ahi[mf][1], ahi[mf][2], ahi[mf][3], sA + off);
                ldsm4(alo[mf][0], alo[mf][1], alo[mf][2], alo[mf][3], sA + 16384 + off);
            }
#pragma unroll
            for (int np = 0; np < 4; np++) {
                int n = warp_n * 64 + np * 16 + (lane & 15);
                uint32_t off = SWZ((uint32_t)(n * 128 + koff));
                uint32_t bh0, bh1, bh2, bh3, bl0, bl1, bl2, bl3;
                ldsm4(bh0, bh1, bh2, bh3, sB + off);
                ldsm4(bl0, bl1, bl2, bl3, sB + 16384 + off);
#pragma unroll
                for (int mf = 0; mf < 2; mf++) {
                    float* c0 = acc[mf][np * 2];
                    float* c1 = acc[mf][np * 2 + 1];
                    mma16816(c0, ahi[mf], bh0, bh2);
                    mma16816(c0, ahi[mf], bl0, bl2);
                    mma16816(c0, alo[mf], bh0, bh2);
                    mma16816(c1, ahi[mf], bh1, bh3);
                    mma16816(c1, ahi[mf], bl1, bl3);
                    mma16816(c1, alo[mf], bh1, bh3);
                }
            }
        }
        __syncthreads();
    }

    // epilogue
    int gid = lane >> 2, tig = lane & 3;
#pragma unroll
    for (int mf = 0; mf < 2; mf++) {
#pragma unroll
        for (int nf = 0; nf < 8; nf++) {
            int col = h * 128 + warp_n * 64 + nf * 8 + tig * 2;
            float2 bv = *(const float2*)(bias + col);
            int row0 = br * 128 + warp_m * 32 + mf * 16 + gid;
            float* c = acc[mf][nf];
            *(float2*)(dst + (size_t)row0 * 256 + col) = make_float2(c[0] + bv.x, c[1] + bv.y);
            *(float2*)(dst + (size_t)(row0 + 8) * 256 + col) = make_float2(c[2] + bv.x, c[3] + bv.y);
        }
    }
}

// ---------------- sorted message kernel: block = dst node, thread = channel ----------------
__global__ __launch_bounds__(256)
void msg_sorted(const float* __restrict__ edge_attr,
                const float* __restrict__ edge_weight,
                const float* __restrict__ bond_W,
                const float* __restrict__ bond_b,
                const int* __restrict__ ei) {
    int d = blockIdx.x;
    int c = threadIdx.x;
    int s0 = g_seg[d], s1 = g_seg[d + 1];
    float bw[16];
#pragma unroll
    for (int k = 0; k < 16; k++) bw[k] = __ldg(&bond_W[k * 256 + c]);
    float bb = __ldg(&bond_b[c]);
    float acc0 = 0.f, acc1 = 0.f, acc2 = 0.f, acc3 = 0.f;
    for (int i = s0; i < s1; i++) {
        int e = g_sorted[i];
        int s = __ldg(&ei[e]);
        const float4* ap = (const float4*)(edge_attr + (size_t)e * 16);
        float4 a0 = __ldg(ap), a1 = __ldg(ap + 1), a2 = __ldg(ap + 2), a3 = __ldg(ap + 3);
        float emb = bb;
        emb = fmaf(a0.x, bw[0], emb);  emb = fmaf(a0.y, bw[1], emb);
        emb = fmaf(a0.z, bw[2], emb);  emb = fmaf(a0.w, bw[3], emb);
        emb = fmaf(a1.x, bw[4], emb);  emb = fmaf(a1.y, bw[5], emb);
        emb = fmaf(a1.z, bw[6], emb);  emb = fmaf(a1.w, bw[7], emb);
        emb = fmaf(a2.x, bw[8], emb);  emb = fmaf(a2.y, bw[9], emb);
        emb = fmaf(a2.z, bw[10], emb); emb = fmaf(a2.w, bw[11], emb);
        emb = fmaf(a3.x, bw[12], emb); emb = fmaf(a3.y, bw[13], emb);
        emb = fmaf(a3.z, bw[14], emb); emb = fmaf(a3.w, bw[15], emb);
        float w0 = __ldg(&edge_weight[e]);
        float w1 = __ldg(&edge_weight[Ee + e]);
        float w2 = __ldg(&edge_weight[2 * Ee + e]);
        float w3 = __ldg(&edge_weight[3 * Ee + e]);
        const float* xr = g_xl + (size_t)s * 256 + c;
        float v0 = xr[0] + emb;
        float v1 = xr[(size_t)Nn * 256] + emb;
        float v2 = xr[(size_t)2 * Nn * 256] + emb;
        float v3 = xr[(size_t)3 * Nn * 256] + emb;
        acc0 += 0.5f * v0 * (1.0f + erff(v0 * 0.70710678118654752f)) * w0;
        acc1 += 0.5f * v1 * (1.0f + erff(v1 * 0.70710678118654752f)) * w1;
        acc2 += 0.5f * v2 * (1.0f + erff(v2 * 0.70710678118654752f)) * w2;
        acc3 += 0.5f * v3 * (1.0f + erff(v3 * 0.70710678118654752f)) * w3;
    }
    float inv = 1.0f / (float)max(s1 - s0, 1);
    float* op = g_sums + (size_t)d * 256 + c;
    op[0] = acc0 * inv;
    op[(size_t)Nn * 256] = acc1 * inv;
    op[(size_t)2 * Nn * 256] = acc2 * inv;
    op[(size_t)3 * Nn * 256] = acc3 * inv;
}

// ---------------------------------------------------------------------------
extern "C" void kernel_launch(void* const* d_in, const int* in_sizes, int n_in,
                              void* d_out, int out_size) {
    const float* x           = (const float*)d_in[0];
    const float* edge_attr   = (const float*)d_in[1];
    const float* edge_weight = (const float*)d_in[2];
    const float* lin_W       = (const float*)d_in[3];
    const float* lin_b       = (const float*)d_in[4];
    const float* linl_W      = (const float*)d_in[5];
    const float* linl_b      = (const float*)d_in[6];
    const float* linr_W      = (const float*)d_in[7];
    const float* bond_W      = (const float*)d_in[8];
    const float* bond_b      = (const float*)d_in[9];
    const int*   ei          = (const int*)d_in[10];
    float* out = (float*)d_out;

    const int SMEM_BYTES = 65536;
    cudaFuncSetAttribute(mm_gemm, cudaFuncAttributeMaxDynamicSharedMemorySize, SMEM_BYTES);

    prep_weights<<<768, 256>>>(lin_W, linl_W, linr_W);
    zero_cnt<<<(Nn + 255) / 256, 256>>>();
    count_kernel<<<(Ee + 255) / 256, 256>>>(ei);
    scan_kernel<<<1, 256>>>();
    scatter_kernel<<<(Ee + 255) / 256, 256>>>(ei);
    mm_gemm<<<dim3(2, 625), 256, SMEM_BYTES>>>(x, lin_b, nullptr, 4, 0);
    msg_sorted<<<Nn, 256>>>(edge_attr, edge_weight, bond_W, bond_b, ei);
    mm_gemm<<<dim3(2, 625), 256, SMEM_BYTES>>>(x, linl_b, out, 8, 1);
}

// round 10
// speedup vs baseline: 1.8803x; 1.0414x over previous
#include <cuda_runtime.h>
#include <cuda_bf16.h>
#include <math.h>
#include <stdint.h>

#define Nn 20000
#define Cc 256
#define Ee 100000
#define RC 4
#define NB 79   // scan blocks: 79*256 = 20224 >= Nn

// ---------------- device scratch ----------------
__device__ float g_xl[RC * Nn * Cc];
__device__ float g_sums[RC * Nn * Cc];     // holds scatter-MEAN after msg_sorted
__device__ int   g_cnt[Nn];
__device__ int   g_seg[Nn + 1];
__device__ int   g_cursor[Nn];
__device__ int   g_sorted[Ee];
__device__ int   g_bsum[NB];
__device__ int   g_boff[NB];
// weight images: [kb][h][hi/lo][8192 bf16]; each = 128 n-rows x 64 k-cols, SW128 swizzled
__device__ __nv_bfloat16 g_B1[4 * 2 * 2 * 8192];
__device__ __nv_bfloat16 g_B2[8 * 2 * 2 * 8192];

__device__ __forceinline__ uint32_t smem_u32(const void* p) {
    uint32_t a;
    asm("{ .reg .u64 t; cvta.to.shared.u64 t, %1; cvt.u32.u64 %0, t; }" : "=r"(a) : "l"(p));
    return a;
}
__host__ __device__ __forceinline__ uint32_t SWZ(uint32_t off) { return off ^ ((off >> 3) & 0x70); }

__device__ __forceinline__ void ldsm4(uint32_t& r0, uint32_t& r1, uint32_t& r2, uint32_t& r3,
                                      uint32_t addr) {
    asm volatile("ldmatrix.sync.aligned.m8n8.x4.shared.b16 {%0,%1,%2,%3}, [%4];"
                 : "=r"(r0), "=r"(r1), "=r"(r2), "=r"(r3) : "r"(addr));
}
__device__ __forceinline__ void mma16816(float* c, const uint32_t* a, uint32_t b0, uint32_t b1) {
    asm volatile(
        "mma.sync.aligned.m16n8k16.row.col.f32.bf16.bf16.f32 "
        "{%0,%1,%2,%3}, {%4,%5,%6,%7}, {%8,%9}, {%0,%1,%2,%3};"
        : "+f"(c[0]), "+f"(c[1]), "+f"(c[2]), "+f"(c[3])
        : "r"(a[0]), "r"(a[1]), "r"(a[2]), "r"(a[3]), "r"(b0), "r"(b1));
}
__device__ __forceinline__ void cp16(uint32_t dst, const void* src) {
    asm volatile("cp.async.cg.shared.global [%0], [%1], 16;" :: "r"(dst), "l"(src));
}

// ---------------- prep / sort kernels ----------------
__global__ void prep_weights(const float* __restrict__ lin_W, const float* __restrict__ linl_W,
                             const float* __restrict__ linr_W) {
    int idx = blockIdx.x * blockDim.x + threadIdx.x;
    if (idx >= 3 * 65536) return;
    int m = idx >> 16;
    int kn = idx & 65535;
    int k = kn >> 8, n = kn & 255;
    const float* W = (m == 0) ? lin_W : ((m == 1) ? linl_W : linr_W);
    float v = W[k * 256 + n];
    __nv_bfloat16 hb = __float2bfloat16(v);
    __nv_bfloat16 lb = __float2bfloat16(v - __bfloat162float(hb));
    int h = n >> 7, np = n & 127, kb = k >> 6, kc = k & 63;
    uint32_t elem = SWZ((uint32_t)(np * 128 + kc * 2)) >> 1;
    if (m == 0) {
        size_t base = ((size_t)(kb * 2 + h) * 2) * 8192;
        g_B1[base + elem] = hb;
        g_B1[base + 8192 + elem] = lb;
    } else {
        int kb2 = (m == 1) ? kb : kb + 4;
        size_t base = ((size_t)(kb2 * 2 + h) * 2) * 8192;
        g_B2[base + elem] = hb;
        g_B2[base + 8192 + elem] = lb;
    }
}

__global__ void zero_cnt() {
    int n = blockIdx.x * blockDim.x + threadIdx.x;
    if (n < Nn) g_cnt[n] = 0;
}
__global__ void count_kernel(const int* __restrict__ ei) {
    int e = blockIdx.x * blockDim.x + threadIdx.x;
    if (e < Ee) atomicAdd(&g_cnt[ei[Ee + e]], 1);
}
// scan stage 1: per-block sums (coalesced)
__global__ void bsum_kernel() {
    __shared__ int ws[8];
    int idx = blockIdx.x * 256 + threadIdx.x;
    int v = (idx < Nn) ? g_cnt[idx] : 0;
    int s = v;
#pragma unroll
    for (int o = 16; o > 0; o >>= 1) s += __shfl_down_sync(0xffffffffu, s, o);
    if ((threadIdx.x & 31) == 0) ws[threadIdx.x >> 5] = s;
    __syncthreads();
    if (threadIdx.x == 0) {
        int t = 0;
#pragma unroll
        for (int i = 0; i < 8; i++) t += ws[i];
        g_bsum[blockIdx.x] = t;
    }
}
// scan stage 2: exclusive scan of NB block sums (1 block)
__global__ void bscan_kernel() {
    __shared__ int s[NB];
    int t = threadIdx.x;
    if (t < NB) s[t] = g_bsum[t];
    __syncthreads();
    if (t == 0) {
        int run = 0;
        for (int i = 0; i < NB; i++) { int v = s[i]; g_boff[i] = run; run += v; }
        g_seg[Nn] = run;
    }
}
// scan stage 3: block-local exclusive scan + offset, zero cursors
__global__ void seg_kernel() {
    __shared__ int s[256];
    int t = threadIdx.x;
    int idx = blockIdx.x * 256 + t;
    int v = (idx < Nn) ? g_cnt[idx] : 0;
    s[t] = v;
    __syncthreads();
#pragma unroll
    for (int o = 1; o < 256; o <<= 1) {
        int nv = (t >= o) ? s[t - o] : 0;
        __syncthreads();
        s[t] += nv;
        __syncthreads();
    }
    if (idx < Nn) {
        g_seg[idx] = g_boff[blockIdx.x] + s[t] - v;   // exclusive
        g_cursor[idx] = 0;
    }
}
__global__ void scatter_kernel(const int* __restrict__ ei) {
    int e = blockIdx.x * blockDim.x + threadIdx.x;
    if (e < Ee) {
        int d = ei[Ee + e];
        int pos = g_seg[d] + atomicAdd(&g_cursor[d], 1);
        g_sorted[pos] = e;
    }
}

// ---------------- split-bf16 mma.sync GEMM, B double-buffered ----------------
// mode 0: g_xl = x @ lin_W + lin_b                           (KB=4)
// mode 1: Out = g_sums @ linl_W + linl_b + x @ linr_W        (KB=8; g_sums already mean-scaled)
__global__ __launch_bounds__(256, 2)
void mm_gemm(const float* __restrict__ X, const float* __restrict__ bias,
             float* __restrict__ Out, int KB, int mode) {
    extern __shared__ __align__(1024) char smem[];
    // AHI 0 (16K), ALO 16384, B buf0 32768 (32K), B buf1 65536 (32K)
    int tid = threadIdx.x, lane = tid & 31, wid = tid >> 5;
    int warp_m = wid & 3, warp_n = wid >> 2;
    int h = blockIdx.x, br = blockIdx.y;

    const __nv_bfloat16* Bimg = mode ? g_B2 : g_B1;
    float* dst = mode ? Out : g_xl;
    uint32_t sA = smem_u32(smem);

    float acc[2][8][4] = {};

    // prologue: B(0) -> buf0
    {
        const uint4* bsrc = (const uint4*)(Bimg + ((size_t)(0 * 2 + h) * 2) * 8192);
        for (int i = tid; i < 2048; i += 256) cp16(sA + 32768 + i * 16, bsrc + i);
        asm volatile("cp.async.commit_group;");
    }

    for (int kb = 0; kb < KB; kb++) {
        uint32_t sB = sA + 32768 + (kb & 1) * 32768;
        // issue B(kb+1) into the other buffer (empty commit on last iter to keep counts aligned)
        if (kb + 1 < KB) {
            uint32_t sBn = sA + 32768 + ((kb + 1) & 1) * 32768;
            const uint4* bsrc = (const uint4*)(Bimg + ((size_t)((kb + 1) * 2 + h) * 2) * 8192);
            for (int i = tid; i < 2048; i += 256) cp16(sBn + i * 16, bsrc + i);
        }
        asm volatile("cp.async.commit_group;");

        // A tile: 128 rows x 64 fp32 -> bf16 hi/lo, SW128 (overlaps with B DMA)
        const float* src;
        int cb;
        if (mode == 1 && kb < 4) { src = g_sums; cb = kb * 64; }
        else { src = X; cb = (mode == 1 ? (kb - 4) * 64 : kb * 64); }
        for (int i = tid; i < 2048; i += 256) {
            int row = i >> 4, q = i & 15;
            float4 v = *(const float4*)(src + (size_t)(br * 128 + row) * 256 + cb + q * 4);
            float fv[4] = {v.x, v.y, v.z, v.w};
            uint32_t hp[2], lp[2];
#pragma unroll
            for (int p = 0; p < 2; p++) {
                __nv_bfloat16 h0 = __float2bfloat16(fv[2 * p]);
                __nv_bfloat16 h1 = __float2bfloat16(fv[2 * p + 1]);
                __nv_bfloat16 l0 = __float2bfloat16(fv[2 * p] - __bfloat162float(h0));
                __nv_bfloat16 l1 = __float2bfloat16(fv[2 * p + 1] - __bfloat162float(h1));
                unsigned short uh0 = *(unsigned short*)&h0, uh1 = *(unsigned short*)&h1;
                unsigned short ul0 = *(unsigned short*)&l0, ul1 = *(unsigned short*)&l1;
                hp[p] = (uint32_t)uh0 | ((uint32_t)uh1 << 16);
                lp[p] = (uint32_t)ul0 | ((uint32_t)ul1 << 16);
            }
            uint32_t sw = SWZ((uint32_t)(row * 128 + q * 8));
            *(uint2*)(smem + sw) = make_uint2(hp[0], hp[1]);
            *(uint2*)(smem + 16384 + sw) = make_uint2(lp[0], lp[1]);
        }
        asm volatile("cp.async.wait_group 1;" ::: "memory");   // B(kb) resident; B(kb+1) in flight
        __syncthreads();

#pragma unroll
        for (int ks = 0; ks < 4; ks++) {
            int koff = ks * 32 + ((lane >> 4) * 16);   // bytes
            uint32_t ahi[2][4], alo[2][4];
#pragma unroll
            for (int mf = 0; mf < 2; mf++) {
                int row = warp_m * 32 + mf * 16 + (lane & 15);
                uint32_t off = SWZ((uint32_t)(row * 128 + koff));
                ldsm4(ahi[mf][0], ahi[mf][1], ahi[mf][2], ahi[mf][3], sA + off);
                ldsm4(alo[mf][0], alo[mf][1], alo[mf][2], alo[mf][3], sA + 16384 + off);
            }
#pragma unroll
            for (int np = 0; np < 4; np++) {
                int n = warp_n * 64 + np * 16 + (lane & 15);
                uint32_t off = SWZ((uint32_t)(n * 128 + koff));
                uint32_t bh0, bh1, bh2, bh3, bl0, bl1, bl2, bl3;
                ldsm4(bh0, bh1, bh2, bh3, sB + off);
                ldsm4(bl0, bl1, bl2, bl3, sB + 16384 + off);
#pragma unroll
                for (int mf = 0; mf < 2; mf++) {
                    float* c0 = acc[mf][np * 2];
                    float* c1 = acc[mf][np * 2 + 1];
                    mma16816(c0, ahi[mf], bh0, bh2);
                    mma16816(c0, ahi[mf], bl0, bl2);
                    mma16816(c0, alo[mf], bh0, bh2);
                    mma16816(c1, ahi[mf], bh1, bh3);
                    mma16816(c1, ahi[mf], bl1, bl3);
                    mma16816(c1, alo[mf], bh1, bh3);
                }
            }
        }
        __syncthreads();
    }

    // epilogue
    int gid = lane >> 2, tig = lane & 3;
#pragma unroll
    for (int mf = 0; mf < 2; mf++) {
#pragma unroll
        for (int nf = 0; nf < 8; nf++) {
            int col = h * 128 + warp_n * 64 + nf * 8 + tig * 2;
            float2 bv = *(const float2*)(bias + col);
            int row0 = br * 128 + warp_m * 32 + mf * 16 + gid;
            float* c = acc[mf][nf];
            *(float2*)(dst + (size_t)row0 * 256 + col) = make_float2(c[0] + bv.x, c[1] + bv.y);
            *(float2*)(dst + (size_t)(row0 + 8) * 256 + col) = make_float2(c[2] + bv.x, c[3] + bv.y);
        }
    }
}

// ---------------- sorted message kernel: block = dst node, thread = channel ----------------
__global__ __launch_bounds__(256)
void msg_sorted(const float* __restrict__ edge_attr,
                const float* __restrict__ edge_weight,
                const float* __restrict__ bond_W,
                const float* __restrict__ bond_b,
                const int* __restrict__ ei) {
    int d = blockIdx.x;
    int c = threadIdx.x;
    int s0 = g_seg[d], s1 = g_seg[d + 1];
    float bw[16];
#pragma unroll
    for (int k = 0; k < 16; k++) bw[k] = __ldg(&bond_W[k * 256 + c]);
    float bb = __ldg(&bond_b[c]);
    float acc0 = 0.f, acc1 = 0.f, acc2 = 0.f, acc3 = 0.f;
    for (int i = s0; i < s1; i++) {
        int e = g_sorted[i];
        int s = __ldg(&ei[e]);
        const float4* ap = (const float4*)(edge_attr + (size_t)e * 16);
        float4 a0 = __ldg(ap), a1 = __ldg(ap + 1), a2 = __ldg(ap + 2), a3 = __ldg(ap + 3);
        float emb = bb;
        emb = fmaf(a0.x, bw[0], emb);  emb = fmaf(a0.y, bw[1], emb);
        emb = fmaf(a0.z, bw[2], emb);  emb = fmaf(a0.w, bw[3], emb);
        emb = fmaf(a1.x, bw[4], emb);  emb = fmaf(a1.y, bw[5], emb);
        emb = fmaf(a1.z, bw[6], emb);  emb = fmaf(a1.w, bw[7], emb);
        emb = fmaf(a2.x, bw[8], emb);  emb = fmaf(a2.y, bw[9], emb);
        emb = fmaf(a2.z, bw[10], emb); emb = fmaf(a2.w, bw[11], emb);
        emb = fmaf(a3.x, bw[12], emb); emb = fmaf(a3.y, bw[13], emb);
        emb = fmaf(a3.z, bw[14], emb); emb = fmaf(a3.w, bw[15], emb);
        float w0 = __ldg(&edge_weight[e]);
        float w1 = __ldg(&edge_weight[Ee + e]);
        float w2 = __ldg(&edge_weight[2 * Ee + e]);
        float w3 = __ldg(&edge_weight[3 * Ee + e]);
        const float* xr = g_xl + (size_t)s * 256 + c;
        float v0 = xr[0] + emb;
        float v1 = xr[(size_t)Nn * 256] + emb;
        float v2 = xr[(size_t)2 * Nn * 256] + emb;
        float v3 = xr[(size_t)3 * Nn * 256] + emb;
        acc0 += 0.5f * v0 * (1.0f + erff(v0 * 0.70710678118654752f)) * w0;
        acc1 += 0.5f * v1 * (1.0f + erff(v1 * 0.70710678118654752f)) * w1;
        acc2 += 0.5f * v2 * (1.0f + erff(v2 * 0.70710678118654752f)) * w2;
        acc3 += 0.5f * v3 * (1.0f + erff(v3 * 0.70710678118654752f)) * w3;
    }
    float inv = 1.0f / (float)max(s1 - s0, 1);
    float* op = g_sums + (size_t)d * 256 + c;
    op[0] = acc0 * inv;
    op[(size_t)Nn * 256] = acc1 * inv;
    op[(size_t)2 * Nn * 256] = acc2 * inv;
    op[(size_t)3 * Nn * 256] = acc3 * inv;
}

// ---------------------------------------------------------------------------
extern "C" void kernel_launch(void* const* d_in, const int* in_sizes, int n_in,
                              void* d_out, int out_size) {
    const float* x           = (const float*)d_in[0];
    const float* edge_attr   = (const float*)d_in[1];
    const float* edge_weight = (const float*)d_in[2];
    const float* lin_W       = (const float*)d_in[3];
    const float* lin_b       = (const float*)d_in[4];
    const float* linl_W      = (const float*)d_in[5];
    const float* linl_b      = (const float*)d_in[6];
    const float* linr_W      = (const float*)d_in[7];
    const float* bond_W      = (const float*)d_in[8];
    const float* bond_b      = (const float*)d_in[9];
    const int*   ei          = (const int*)d_in[10];
    float* out = (float*)d_out;

    const int SMEM_BYTES = 32768 + 2 * 32768;   // 98304
    cudaFuncSetAttribute(mm_gemm, cudaFuncAttributeMaxDynamicSharedMemorySize, SMEM_BYTES);

    zero_cnt<<<(Nn + 255) / 256, 256>>>();                       // 0
    count_kernel<<<(Ee + 255) / 256, 256>>>(ei);                 // 1
    prep_weights<<<768, 256>>>(lin_W, linl_W, linr_W);           // 2
    mm_gemm<<<dim3(2, 625), 256, SMEM_BYTES>>>(x, lin_b, nullptr, 4, 0);   // 3 <- profiled
    bsum_kernel<<<NB, 256>>>();                                  // 4
    bscan_kernel<<<1, 128>>>();                                  // 5
    seg_kernel<<<NB, 256>>>();                                   // 6
    scatter_kernel<<<(Ee + 255) / 256, 256>>>(ei);               // 7
    msg_sorted<<<Nn, 256>>>(edge_attr, edge_weight, bond_W, bond_b, ei);   // 8
    mm_gemm<<<dim3(2, 625), 256, SMEM_BYTES>>>(x, linl_b, out, 8, 1);      // 9
}

// round 11
// speedup vs baseline: 1.9770x; 1.0514x over previous
#include <cuda_runtime.h>
#include <cuda_bf16.h>
#include <math.h>
#include <stdint.h>

#define Nn 20000
#define Cc 256
#define Ee 100000
#define RC 4
#define NB 79   // scan blocks: 79*256 = 20224 >= Nn

// ---------------- device scratch ----------------
__device__ float g_xl[RC * Nn * Cc];
__device__ int   g_cnt[Nn];
__device__ int   g_seg[Nn + 1];
__device__ int   g_cursor[Nn];
__device__ int   g_sorted[Ee];
__device__ int   g_bsum[NB];
__device__ int   g_boff[NB];
// Pre-swizzled bf16 operand images. Each (row-block, kb) unit = 32768 bytes:
// hi image (128x64, SW128) at +0, lo image at +16384.
__device__ __nv_bfloat16 g_Ax[625 * 4 * 2 * 8192];     // x converted
__device__ __nv_bfloat16 g_Asum[625 * 4 * 2 * 8192];   // scatter-mean converted
__device__ __nv_bfloat16 g_B1[4 * 2 * 2 * 8192];       // lin_W
__device__ __nv_bfloat16 g_B2[8 * 2 * 2 * 8192];       // linl_W | linr_W

__device__ __forceinline__ uint32_t smem_u32(const void* p) {
    uint32_t a;
    asm("{ .reg .u64 t; cvta.to.shared.u64 t, %1; cvt.u32.u64 %0, t; }" : "=r"(a) : "l"(p));
    return a;
}
__host__ __device__ __forceinline__ uint32_t SWZ(uint32_t off) { return off ^ ((off >> 3) & 0x70); }

__device__ __forceinline__ void ldsm4(uint32_t& r0, uint32_t& r1, uint32_t& r2, uint32_t& r3,
                                      uint32_t addr) {
    asm volatile("ldmatrix.sync.aligned.m8n8.x4.shared.b16 {%0,%1,%2,%3}, [%4];"
                 : "=r"(r0), "=r"(r1), "=r"(r2), "=r"(r3) : "r"(addr));
}
__device__ __forceinline__ void mma16816(float* c, const uint32_t* a, uint32_t b0, uint32_t b1) {
    asm volatile(
        "mma.sync.aligned.m16n8k16.row.col.f32.bf16.bf16.f32 "
        "{%0,%1,%2,%3}, {%4,%5,%6,%7}, {%8,%9}, {%0,%1,%2,%3};"
        : "+f"(c[0]), "+f"(c[1]), "+f"(c[2]), "+f"(c[3])
        : "r"(a[0]), "r"(a[1]), "r"(a[2]), "r"(a[3]), "r"(b0), "r"(b1));
}
__device__ __forceinline__ void cp16(uint32_t dst, const void* src) {
    asm volatile("cp.async.cg.shared.global [%0], [%1], 16;" :: "r"(dst), "l"(src));
}
__device__ __forceinline__ void split_bf16(float v, unsigned short& h, unsigned short& l) {
    __nv_bfloat16 hb = __float2bfloat16(v);
    __nv_bfloat16 lb = __float2bfloat16(v - __bfloat162float(hb));
    h = *(unsigned short*)&hb;
    l = *(unsigned short*)&lb;
}

// ---------------- conversion / prep kernels ----------------
// x (80000x256 fp32) -> g_Ax swizzled hi/lo images. 20000 blocks x 256 threads, 1 float4/thread.
__global__ void conv_x(const float* __restrict__ x) {
    int idx = blockIdx.x * 256 + threadIdx.x;
    int m = idx >> 6, q = idx & 63;
    float4 v = *(const float4*)(x + (size_t)m * 256 + q * 4);
    unsigned short h0, h1, h2, h3, l0, l1, l2, l3;
    split_bf16(v.x, h0, l0); split_bf16(v.y, h1, l1);
    split_bf16(v.z, h2, l2); split_bf16(v.w, h3, l3);
    uint2 hp = make_uint2((uint32_t)h0 | ((uint32_t)h1 << 16), (uint32_t)h2 | ((uint32_t)h3 << 16));
    uint2 lp = make_uint2((uint32_t)l0 | ((uint32_t)l1 << 16), (uint32_t)l2 | ((uint32_t)l3 << 16));
    int kb = q >> 4, qq = q & 15;
    char* base = (char*)g_Ax + ((size_t)((m >> 7) * 4 + kb)) * 32768;
    uint32_t off = SWZ((uint32_t)((m & 127) * 128 + qq * 8));
    *(uint2*)(base + off) = hp;
    *(uint2*)(base + 16384 + off) = lp;
}

__global__ void prep_weights(const float* __restrict__ lin_W, const float* __restrict__ linl_W,
                             const float* __restrict__ linr_W) {
    int idx = blockIdx.x * blockDim.x + threadIdx.x;
    if (idx >= 3 * 65536) return;
    int m = idx >> 16;
    int kn = idx & 65535;
    int k = kn >> 8, n = kn & 255;
    const float* W = (m == 0) ? lin_W : ((m == 1) ? linl_W : linr_W);
    float v = W[k * 256 + n];
    __nv_bfloat16 hb = __float2bfloat16(v);
    __nv_bfloat16 lb = __float2bfloat16(v - __bfloat162float(hb));
    int h = n >> 7, np = n & 127, kb = k >> 6, kc = k & 63;
    uint32_t elem = SWZ((uint32_t)(np * 128 + kc * 2)) >> 1;
    if (m == 0) {
        size_t base = ((size_t)(kb * 2 + h) * 2) * 8192;
        g_B1[base + elem] = hb;
        g_B1[base + 8192 + elem] = lb;
    } else {
        int kb2 = (m == 1) ? kb : kb + 4;
        size_t base = ((size_t)(kb2 * 2 + h) * 2) * 8192;
        g_B2[base + elem] = hb;
        g_B2[base + 8192 + elem] = lb;
    }
}

__global__ void zero_cnt() {
    int n = blockIdx.x * blockDim.x + threadIdx.x;
    if (n < Nn) g_cnt[n] = 0;
}
__global__ void count_kernel(const int* __restrict__ ei) {
    int e = blockIdx.x * blockDim.x + threadIdx.x;
    if (e < Ee) atomicAdd(&g_cnt[ei[Ee + e]], 1);
}
__global__ void bsum_kernel() {
    __shared__ int ws[8];
    int idx = blockIdx.x * 256 + threadIdx.x;
    int v = (idx < Nn) ? g_cnt[idx] : 0;
    int s = v;
#pragma unroll
    for (int o = 16; o > 0; o >>= 1) s += __shfl_down_sync(0xffffffffu, s, o);
    if ((threadIdx.x & 31) == 0) ws[threadIdx.x >> 5] = s;
    __syncthreads();
    if (threadIdx.x == 0) {
        int t = 0;
#pragma unroll
        for (int i = 0; i < 8; i++) t += ws[i];
        g_bsum[blockIdx.x] = t;
    }
}
__global__ void bscan_kernel() {
    int t = threadIdx.x;
    if (t == 0) {
        int run = 0;
        for (int i = 0; i < NB; i++) { int v = g_bsum[i]; g_boff[i] = run; run += v; }
        g_seg[Nn] = run;
    }
}
__global__ void seg_kernel() {
    __shared__ int s[256];
    int t = threadIdx.x;
    int idx = blockIdx.x * 256 + t;
    int v = (idx < Nn) ? g_cnt[idx] : 0;
    s[t] = v;
    __syncthreads();
#pragma unroll
    for (int o = 1; o < 256; o <<= 1) {
        int nv = (t >= o) ? s[t - o] : 0;
        __syncthreads();
        s[t] += nv;
        __syncthreads();
    }
    if (idx < Nn) {
        g_seg[idx] = g_boff[blockIdx.x] + s[t] - v;
        g_cursor[idx] = 0;
    }
}
__global__ void scatter_kernel(const int* __restrict__ ei) {
    int e = blockIdx.x * blockDim.x + threadIdx.x;
    if (e < Ee) {
        int d = ei[Ee + e];
        int pos = g_seg[d] + atomicAdd(&g_cursor[d], 1);
        g_sorted[pos] = e;
    }
}

// ---------------- pure-MMA GEMM (all operands pre-swizzled bf16 images) ----------------
// mode 0: g_xl = x @ lin_W + lin_b                           (KB=4)
// mode 1: Out = mean @ linl_W + linl_b + x @ linr_W          (KB=8)
__global__ __launch_bounds__(256, 2)
void mm_gemm(const float* __restrict__ bias, float* __restrict__ Out, int KB, int mode) {
    extern __shared__ __align__(1024) char smem[];
    // A buf0 @0 (32K: hi 16K + lo 16K), A buf1 @32768, B @65536 (32K)
    int tid = threadIdx.x, lane = tid & 31, wid = tid >> 5;
    int warp_m = wid & 3, warp_n = wid >> 2;
    int h = blockIdx.x, br = blockIdx.y;

    const __nv_bfloat16* Bimg = mode ? g_B2 : g_B1;
    float* dst = mode ? Out : g_xl;
    uint32_t sbase = smem_u32(smem);

    auto asrc = [&](int kb) -> const char* {
        if (mode == 1 && kb < 4)
            return (const char*)g_Asum + ((size_t)(br * 4 + kb)) * 32768;
        int kk = mode ? kb - 4 : kb;
        return (const char*)g_Ax + ((size_t)(br * 4 + kk)) * 32768;
    };

    float acc[2][8][4] = {};

    // prologue: A(0) -> buf0 ; B(0)
    {
        const uint4* ap = (const uint4*)asrc(0);
        for (int i = tid; i < 2048; i += 256) cp16(sbase + i * 16, ap + i);
        asm volatile("cp.async.commit_group;");
        const uint4* bp = (const uint4*)(Bimg + ((size_t)(0 * 2 + h) * 2) * 8192);
        for (int i = tid; i < 2048; i += 256) cp16(sbase + 65536 + i * 16, bp + i);
        asm volatile("cp.async.commit_group;");
    }

    for (int kb = 0; kb < KB; kb++) {
        uint32_t sA = sbase + (kb & 1) * 32768;
        uint32_t sB = sbase + 65536;
        if (kb + 1 < KB) {   // prefetch A(kb+1)
            uint32_t sAn = sbase + ((kb + 1) & 1) * 32768;
            const uint4* ap = (const uint4*)asrc(kb + 1);
            for (int i = tid; i < 2048; i += 256) cp16(sAn + i * 16, ap + i);
            asm volatile("cp.async.commit_group;");
            asm volatile("cp.async.wait_group 1;" ::: "memory");
        } else {
            asm volatile("cp.async.wait_group 0;" ::: "memory");
        }
        __syncthreads();

#pragma unroll
        for (int ks = 0; ks < 4; ks++) {
            int koff = ks * 32 + ((lane >> 4) * 16);   // bytes
            uint32_t ahi[2][4], alo[2][4];
#pragma unroll
            for (int mf = 0; mf < 2; mf++) {
                int row = warp_m * 32 + mf * 16 + (lane & 15);
                uint32_t off = SWZ((uint32_t)(row * 128 + koff));
                ldsm4(ahi[mf][0], ahi[mf][1], ahi[mf][2], ahi[mf][3], sA + off);
                ldsm4(alo[mf][0], alo[mf][1], alo[mf][2], alo[mf][3], sA + 16384 + off);
            }
#pragma unroll
            for (int np = 0; np < 4; np++) {
                int n = warp_n * 64 + np * 16 + (lane & 15);
                uint32_t off = SWZ((uint32_t)(n * 128 + koff));
                uint32_t bh0, bh1, bh2, bh3, bl0, bl1, bl2, bl3;
                ldsm4(bh0, bh1, bh2, bh3, sB + off);
                ldsm4(bl0, bl1, bl2, bl3, sB + 16384 + off);
#pragma unroll
                for (int mf = 0; mf < 2; mf++) {
                    float* c0 = acc[mf][np * 2];
                    float* c1 = acc[mf][np * 2 + 1];
                    mma16816(c0, ahi[mf], bh0, bh2);
                    mma16816(c0, ahi[mf], bl0, bl2);
                    mma16816(c0, alo[mf], bh0, bh2);
                    mma16816(c1, ahi[mf], bh1, bh3);
                    mma16816(c1, ahi[mf], bl1, bl3);
                    mma16816(c1, alo[mf], bh1, bh3);
                }
            }
        }
        __syncthreads();
        if (kb + 1 < KB) {   // refill B(kb+1) after compute released the buffer
            const uint4* bp = (const uint4*)(Bimg + ((size_t)((kb + 1) * 2 + h) * 2) * 8192);
            for (int i = tid; i < 2048; i += 256) cp16(sB + i * 16, bp + i);
            asm volatile("cp.async.commit_group;");
        }
    }

    // epilogue
    int gid = lane >> 2, tig = lane & 3;
#pragma unroll
    for (int mf = 0; mf < 2; mf++) {
#pragma unroll
        for (int nf = 0; nf < 8; nf++) {
            int col = h * 128 + warp_n * 64 + nf * 8 + tig * 2;
            float2 bv = *(const float2*)(bias + col);
            int row0 = br * 128 + warp_m * 32 + mf * 16 + gid;
            float* c = acc[mf][nf];
            *(float2*)(dst + (size_t)row0 * 256 + col) = make_float2(c[0] + bv.x, c[1] + bv.y);
            *(float2*)(dst + (size_t)(row0 + 8) * 256 + col) = make_float2(c[2] + bv.x, c[3] + bv.y);
        }
    }
}

// ---------------- sorted message kernel: emits bf16 hi/lo images directly ----------------
__global__ __launch_bounds__(256)
void msg_sorted(const float* __restrict__ edge_attr,
                const float* __restrict__ edge_weight,
                const float* __restrict__ bond_W,
                const float* __restrict__ bond_b,
                const int* __restrict__ ei) {
    int d = blockIdx.x;
    int c = threadIdx.x;
    int s0 = g_seg[d], s1 = g_seg[d + 1];
    float bw[16];
#pragma unroll
    for (int k = 0; k < 16; k++) bw[k] = __ldg(&bond_W[k * 256 + c]);
    float bb = __ldg(&bond_b[c]);
    float acc0 = 0.f, acc1 = 0.f, acc2 = 0.f, acc3 = 0.f;
    for (int i = s0; i < s1; i++) {
        int e = g_sorted[i];
        int s = __ldg(&ei[e]);
        const float4* ap = (const float4*)(edge_attr + (size_t)e * 16);
        float4 a0 = __ldg(ap), a1 = __ldg(ap + 1), a2 = __ldg(ap + 2), a3 = __ldg(ap + 3);
        float emb = bb;
        emb = fmaf(a0.x, bw[0], emb);  emb = fmaf(a0.y, bw[1], emb);
        emb = fmaf(a0.z, bw[2], emb);  emb = fmaf(a0.w, bw[3], emb);
        emb = fmaf(a1.x, bw[4], emb);  emb = fmaf(a1.y, bw[5], emb);
        emb = fmaf(a1.z, bw[6], emb);  emb = fmaf(a1.w, bw[7], emb);
        emb = fmaf(a2.x, bw[8], emb);  emb = fmaf(a2.y, bw[9], emb);
        emb = fmaf(a2.z, bw[10], emb); emb = fmaf(a2.w, bw[11], emb);
        emb = fmaf(a3.x, bw[12], emb); emb = fmaf(a3.y, bw[13], emb);
        emb = fmaf(a3.z, bw[14], emb); emb = fmaf(a3.w, bw[15], emb);
        float w0 = __ldg(&edge_weight[e]);
        float w1 = __ldg(&edge_weight[Ee + e]);
        float w2 = __ldg(&edge_weight[2 * Ee + e]);
        float w3 = __ldg(&edge_weight[3 * Ee + e]);
        const float* xr = g_xl + (size_t)s * 256 + c;
        float v0 = xr[0] + emb;
        float v1 = xr[(size_t)Nn * 256] + emb;
        float v2 = xr[(size_t)2 * Nn * 256] + emb;
        float v3 = xr[(size_t)3 * Nn * 256] + emb;
        acc0 += 0.5f * v0 * (1.0f + erff(v0 * 0.70710678118654752f)) * w0;
        acc1 += 0.5f * v1 * (1.0f + erff(v1 * 0.70710678118654752f)) * w1;
        acc2 += 0.5f * v2 * (1.0f + erff(v2 * 0.70710678118654752f)) * w2;
        acc3 += 0.5f * v3 * (1.0f + erff(v3 * 0.70710678118654752f)) * w3;
    }
    float inv = 1.0f / (float)max(s1 - s0, 1);
    float vals[4] = {acc0 * inv, acc1 * inv, acc2 * inv, acc3 * inv};
    int kb = c >> 6, kc = c & 63;
#pragma unroll
    for (int rc = 0; rc < 4; rc++) {
        int m = rc * Nn + d;
        char* base = (char*)g_Asum + ((size_t)((m >> 7) * 4 + kb)) * 32768;
        uint32_t off = SWZ((uint32_t)((m & 127) * 128 + kc * 2));
        unsigned short hb, lb;
        split_bf16(vals[rc], hb, lb);
        *(unsigned short*)(base + off) = hb;
        *(unsigned short*)(base + 16384 + off) = lb;
    }
}

// ---------------------------------------------------------------------------
extern "C" void kernel_launch(void* const* d_in, const int* in_sizes, int n_in,
                              void* d_out, int out_size) {
    const float* x           = (const float*)d_in[0];
    const float* edge_attr   = (const float*)d_in[1];
    const float* edge_weight = (const float*)d_in[2];
    const float* lin_W       = (const float*)d_in[3];
    const float* lin_b       = (const float*)d_in[4];
    const float* linl_W      = (const float*)d_in[5];
    const float* linl_b      = (const float*)d_in[6];
    const float* linr_W      = (const float*)d_in[7];
    const float* bond_W      = (const float*)d_in[8];
    const float* bond_b      = (const float*)d_in[9];
    const int*   ei          = (const int*)d_in[10];
    float* out = (float*)d_out;

    const int SMEM_BYTES = 96 * 1024;
    cudaFuncSetAttribute(mm_gemm, cudaFuncAttributeMaxDynamicSharedMemorySize, SMEM_BYTES);

    zero_cnt<<<(Nn + 255) / 256, 256>>>();                       // 0
    conv_x<<<20000, 256>>>(x);                                   // 1
    prep_weights<<<768, 256>>>(lin_W, linl_W, linr_W);           // 2
    mm_gemm<<<dim3(2, 625), 256, SMEM_BYTES>>>(lin_b, nullptr, 4, 0);   // 3 <- profiled
    count_kernel<<<(Ee + 255) / 256, 256>>>(ei);                 // 4
    bsum_kernel<<<NB, 256>>>();                                  // 5
    bscan_kernel<<<1, 32>>>();                                   // 6
    seg_kernel<<<NB, 256>>>();                                   // 7
    scatter_kernel<<<(Ee + 255) / 256, 256>>>(ei);               // 8
    msg_sorted<<<Nn, 256>>>(edge_attr, edge_weight, bond_W, bond_b, ei); // 9
    mm_gemm<<<dim3(2, 625), 256, SMEM_BYTES>>>(linl_b, out, 8, 1);       // 10
}

// round 14
// speedup vs baseline: 2.0906x; 1.0575x over previous
#include <cuda_runtime.h>
#include <cuda_bf16.h>
#include <math.h>
#include <stdint.h>

#define Nn 20000
#define Cc 256
#define Ee 100000
#define RC 4
#define NB 79     // scan blocks: 79*256 = 20224 >= Nn
#define DEGC 64   // edge chunk per staging pass

// ---------------- device scratch ----------------
__device__ float g_xl[RC * Nn * Cc];
__device__ int   g_cnt[Nn];
__device__ int   g_seg[Nn + 1];
__device__ int   g_cursor[Nn];
__device__ int   g_sorted[Ee];
__device__ int   g_bsum[NB];
__device__ int   g_boff[NB];
// Pre-swizzled bf16 operand images. Each (row-block, kb) unit = 32768 bytes:
// hi image (128x64, SW128) at +0, lo image at +16384.
__device__ __nv_bfloat16 g_Ax[625 * 4 * 2 * 8192];     // x converted
__device__ __nv_bfloat16 g_Asum[625 * 4 * 2 * 8192];   // scatter-mean converted
__device__ __nv_bfloat16 g_B1[4 * 2 * 2 * 8192];       // lin_W
__device__ __nv_bfloat16 g_B2[8 * 2 * 2 * 8192];       // linl_W | linr_W

__device__ __forceinline__ uint32_t smem_u32(const void* p) {
    uint32_t a;
    asm("{ .reg .u64 t; cvta.to.shared.u64 t, %1; cvt.u32.u64 %0, t; }" : "=r"(a) : "l"(p));
    return a;
}
__host__ __device__ __forceinline__ uint32_t SWZ(uint32_t off) { return off ^ ((off >> 3) & 0x70); }

__device__ __forceinline__ void ldsm4(uint32_t& r0, uint32_t& r1, uint32_t& r2, uint32_t& r3,
                                      uint32_t addr) {
    asm volatile("ldmatrix.sync.aligned.m8n8.x4.shared.b16 {%0,%1,%2,%3}, [%4];"
                 : "=r"(r0), "=r"(r1), "=r"(r2), "=r"(r3) : "r"(addr));
}
__device__ __forceinline__ void mma16816(float* c, const uint32_t* a, uint32_t b0, uint32_t b1) {
    asm volatile(
        "mma.sync.aligned.m16n8k16.row.col.f32.bf16.bf16.f32 "
        "{%0,%1,%2,%3}, {%4,%5,%6,%7}, {%8,%9}, {%0,%1,%2,%3};"
        : "+f"(c[0]), "+f"(c[1]), "+f"(c[2]), "+f"(c[3])
        : "r"(a[0]), "r"(a[1]), "r"(a[2]), "r"(a[3]), "r"(b0), "r"(b1));
}
__device__ __forceinline__ void cp16(uint32_t dst, const void* src) {
    asm volatile("cp.async.cg.shared.global [%0], [%1], 16;" :: "r"(dst), "l"(src));
}
__device__ __forceinline__ void split_bf16(float v, unsigned short& h, unsigned short& l) {
    __nv_bfloat16 hb = __float2bfloat16(v);
    __nv_bfloat16 lb = __float2bfloat16(v - __bfloat162float(hb));
    h = *(unsigned short*)&hb;
    l = *(unsigned short*)&lb;
}

// ---------------- conversion / prep kernels ----------------
__global__ void conv_x(const float* __restrict__ x) {
    int idx = blockIdx.x * 256 + threadIdx.x;
    int m = idx >> 6, q = idx & 63;
    float4 v = *(const float4*)(x + (size_t)m * 256 + q * 4);
    unsigned short h0, h1, h2, h3, l0, l1, l2, l3;
    split_bf16(v.x, h0, l0); split_bf16(v.y, h1, l1);
    split_bf16(v.z, h2, l2); split_bf16(v.w, h3, l3);
    uint2 hp = make_uint2((uint32_t)h0 | ((uint32_t)h1 << 16), (uint32_t)h2 | ((uint32_t)h3 << 16));
    uint2 lp = make_uint2((uint32_t)l0 | ((uint32_t)l1 << 16), (uint32_t)l2 | ((uint32_t)l3 << 16));
    int kb = q >> 4, qq = q & 15;
    char* base = (char*)g_Ax + ((size_t)((m >> 7) * 4 + kb)) * 32768;
    uint32_t off = SWZ((uint32_t)((m & 127) * 128 + qq * 8));
    *(uint2*)(base + off) = hp;
    *(uint2*)(base + 16384 + off) = lp;
}

__global__ void prep_weights(const float* __restrict__ lin_W, const float* __restrict__ linl_W,
                             const float* __restrict__ linr_W) {
    int idx = blockIdx.x * blockDim.x + threadIdx.x;
    if (idx >= 3 * 65536) return;
    int m = idx >> 16;
    int kn = idx & 65535;
    int k = kn >> 8, n = kn & 255;
    const float* W = (m == 0) ? lin_W : ((m == 1) ? linl_W : linr_W);
    float v = W[k * 256 + n];
    __nv_bfloat16 hb = __float2bfloat16(v);
    __nv_bfloat16 lb = __float2bfloat16(v - __bfloat162float(hb));
    int h = n >> 7, np = n & 127, kb = k >> 6, kc = k & 63;
    uint32_t elem = SWZ((uint32_t)(np * 128 + kc * 2)) >> 1;
    if (m == 0) {
        size_t base = ((size_t)(kb * 2 + h) * 2) * 8192;
        g_B1[base + elem] = hb;
        g_B1[base + 8192 + elem] = lb;
    } else {
        int kb2 = (m == 1) ? kb : kb + 4;
        size_t base = ((size_t)(kb2 * 2 + h) * 2) * 8192;
        g_B2[base + elem] = hb;
        g_B2[base + 8192 + elem] = lb;
    }
}

__global__ void zero_cnt() {
    int n = blockIdx.x * blockDim.x + threadIdx.x;
    if (n < Nn) g_cnt[n] = 0;
}
__global__ void count_kernel(const int* __restrict__ ei) {
    int e = blockIdx.x * blockDim.x + threadIdx.x;
    if (e < Ee) atomicAdd(&g_cnt[ei[Ee + e]], 1);
}
__global__ void bsum_kernel() {
    __shared__ int ws[8];
    int idx = blockIdx.x * 256 + threadIdx.x;
    int v = (idx < Nn) ? g_cnt[idx] : 0;
    int s = v;
#pragma unroll
    for (int o = 16; o > 0; o >>= 1) s += __shfl_down_sync(0xffffffffu, s, o);
    if ((threadIdx.x & 31) == 0) ws[threadIdx.x >> 5] = s;
    __syncthreads();
    if (threadIdx.x == 0) {
        int t = 0;
#pragma unroll
        for (int i = 0; i < 8; i++) t += ws[i];
        g_bsum[blockIdx.x] = t;
    }
}
__global__ void bscan_kernel() {
    if (threadIdx.x == 0) {
        int run = 0;
        for (int i = 0; i < NB; i++) { int v = g_bsum[i]; g_boff[i] = run; run += v; }
        g_seg[Nn] = run;
    }
}
__global__ void seg_kernel() {
    __shared__ int s[256];
    int t = threadIdx.x;
    int idx = blockIdx.x * 256 + t;
    int v = (idx < Nn) ? g_cnt[idx] : 0;
    s[t] = v;
    __syncthreads();
#pragma unroll
    for (int o = 1; o < 256; o <<= 1) {
        int nv = (t >= o) ? s[t - o] : 0;
        __syncthreads();
        s[t] += nv;
        __syncthreads();
    }
    if (idx < Nn) {
        g_seg[idx] = g_boff[blockIdx.x] + s[t] - v;
        g_cursor[idx] = 0;
    }
}
__global__ void scatter_kernel(const int* __restrict__ ei) {
    int e = blockIdx.x * blockDim.x + threadIdx.x;
    if (e < Ee) {
        int d = ei[Ee + e];
        int pos = g_seg[d] + atomicAdd(&g_cursor[d], 1);
        g_sorted[pos] = e;
    }
}

// ---------------- pure-MMA GEMM (all operands pre-swizzled bf16 images) ----------------
__global__ __launch_bounds__(256, 2)
void mm_gemm(const float* __restrict__ bias, float* __restrict__ Out, int KB, int mode) {
    extern __shared__ __align__(1024) char smem[];
    int tid = threadIdx.x, lane = tid & 31, wid = tid >> 5;
    int warp_m = wid & 3, warp_n = wid >> 2;
    int h = blockIdx.x, br = blockIdx.y;

    const __nv_bfloat16* Bimg = mode ? g_B2 : g_B1;
    float* dst = mode ? Out : g_xl;
    uint32_t sbase = smem_u32(smem);

    auto asrc = [&](int kb) -> const char* {
        if (mode == 1 && kb < 4)
            return (const char*)g_Asum + ((size_t)(br * 4 + kb)) * 32768;
        int kk = mode ? kb - 4 : kb;
        return (const char*)g_Ax + ((size_t)(br * 4 + kk)) * 32768;
    };

    float acc[2][8][4] = {};

    {
        const uint4* ap = (const uint4*)asrc(0);
        for (int i = tid; i < 2048; i += 256) cp16(sbase + i * 16, ap + i);
        asm volatile("cp.async.commit_group;");
        const uint4* bp = (const uint4*)(Bimg + ((size_t)(0 * 2 + h) * 2) * 8192);
        for (int i = tid; i < 2048; i += 256) cp16(sbase + 65536 + i * 16, bp + i);
        asm volatile("cp.async.commit_group;");
    }

    for (int kb = 0; kb < KB; kb++) {
        uint32_t sA = sbase + (kb & 1) * 32768;
        uint32_t sB = sbase + 65536;
        if (kb + 1 < KB) {
            uint32_t sAn = sbase + ((kb + 1) & 1) * 32768;
            const uint4* ap = (const uint4*)asrc(kb + 1);
            for (int i = tid; i < 2048; i += 256) cp16(sAn + i * 16, ap + i);
            asm volatile("cp.async.commit_group;");
            asm volatile("cp.async.wait_group 1;" ::: "memory");
        } else {
            asm volatile("cp.async.wait_group 0;" ::: "memory");
        }
        __syncthreads();

#pragma unroll
        for (int ks = 0; ks < 4; ks++) {
            int koff = ks * 32 + ((lane >> 4) * 16);
            uint32_t ahi[2][4], alo[2][4];
#pragma unroll
            for (int mf = 0; mf < 2; mf++) {
                int row = warp_m * 32 + mf * 16 + (lane & 15);
                uint32_t off = SWZ((uint32_t)(row * 128 + koff));
                ldsm4(ahi[mf][0], ahi[mf][1], ahi[mf][2], ahi[mf][3], sA + off);
                ldsm4(alo[mf][0], alo[mf][1], alo[mf][2], alo[mf][3], sA + 16384 + off);
            }
#pragma unroll
            for (int np = 0; np < 4; np++) {
                int n = warp_n * 64 + np * 16 + (lane & 15);
                uint32_t off = SWZ((uint32_t)(n * 128 + koff));
                uint32_t bh0, bh1, bh2, bh3, bl0, bl1, bl2, bl3;
                ldsm4(bh0, bh1, bh2, bh3, sB + off);
                ldsm4(bl0, bl1, bl2, bl3, sB + 16384 + off);
#pragma unroll
                for (int mf = 0; mf < 2; mf++) {
                    float* c0 = acc[mf][np * 2];
                    float* c1 = acc[mf][np * 2 + 1];
                    mma16816(c0, ahi[mf], bh0, bh2);
                    mma16816(c0, ahi[mf], bl0, bl2);
                    mma16816(c0, alo[mf], bh0, bh2);
                    mma16816(c1, ahi[mf], bh1, bh3);
                    mma16816(c1, ahi[mf], bl1, bl3);
                    mma16816(c1, alo[mf], bh1, bh3);
                }
            }
        }
        __syncthreads();
        if (kb + 1 < KB) {
            const uint4* bp = (const uint4*)(Bimg + ((size_t)((kb + 1) * 2 + h) * 2) * 8192);
            for (int i = tid; i < 2048; i += 256) cp16(sB + i * 16, bp + i);
            asm volatile("cp.async.commit_group;");
        }
    }

    int gid = lane >> 2, tig = lane & 3;
#pragma unroll
    for (int mf = 0; mf < 2; mf++) {
#pragma unroll
        for (int nf = 0; nf < 8; nf++) {
            int col = h * 128 + warp_n * 64 + nf * 8 + tig * 2;
            float2 bv = *(const float2*)(bias + col);
            int row0 = br * 128 + warp_m * 32 + mf * 16 + gid;
            float* c = acc[mf][nf];
            *(float2*)(dst + (size_t)row0 * 256 + col) = make_float2(c[0] + bv.x, c[1] + bv.y);
            *(float2*)(dst + (size_t)(row0 + 8) * 256 + col) = make_float2(c[2] + bv.x, c[3] + bv.y);
        }
    }
}

// ---------------- sorted message kernel: smem-staged edge metadata ----------------
__global__ __launch_bounds__(256)
void msg_sorted(const float* __restrict__ edge_attr,
                const float* __restrict__ edge_weight,
                const float* __restrict__ bond_W,
                const float* __restrict__ bond_b,
                const int* __restrict__ ei) {
    __shared__ int   s_e[DEGC];
    __shared__ int   s_src[DEGC];
    __shared__ float s_w[4][DEGC];
    __shared__ float s_attr[DEGC][16];
    int d = blockIdx.x;
    int c = threadIdx.x;
    int s0 = g_seg[d], s1 = g_seg[d + 1];
    int deg = s1 - s0;
    float bw[16];
#pragma unroll
    for (int k = 0; k < 16; k++) bw[k] = __ldg(&bond_W[k * 256 + c]);
    float bb = __ldg(&bond_b[c]);
    float acc0 = 0.f, acc1 = 0.f, acc2 = 0.f, acc3 = 0.f;

    for (int base = 0; base < deg; base += DEGC) {
        int nb = min(DEGC, deg - base);
        __syncthreads();   // protect smem reuse across chunks
        // stage 1: edge ids + src + weights (one thread per edge; loads parallel across edges)
        if (c < nb) {
            int e = g_sorted[s0 + base + c];
            s_e[c] = e;
            s_src[c] = __ldg(&ei[e]);
            s_w[0][c] = __ldg(&edge_weight[e]);
            s_w[1][c] = __ldg(&edge_weight[Ee + e]);
            s_w[2][c] = __ldg(&edge_weight[2 * Ee + e]);
            s_w[3][c] = __ldg(&edge_weight[3 * Ee + e]);
        }
        __syncthreads();
        // stage 2: attrs (cooperative, float4 per thread-slot)
        for (int i = c; i < nb * 4; i += 256) {
            int j = i >> 2, q = i & 3;
            float4 a = __ldg((const float4*)(edge_attr + (size_t)s_e[j] * 16) + q);
            s_attr[j][q * 4 + 0] = a.x;
            s_attr[j][q * 4 + 1] = a.y;
            s_attr[j][q * 4 + 2] = a.z;
            s_attr[j][q * 4 + 3] = a.w;
        }
        __syncthreads();
        // stage 3: channel loop — all addresses known, loads independent across j
#pragma unroll 4
        for (int j = 0; j < nb; j++) {
            int s = s_src[j];
            const float* xr = g_xl + (size_t)s * 256 + c;
            float x0 = xr[0];
            float x1 = xr[(size_t)Nn * 256];
            float x2 = xr[(size_t)2 * Nn * 256];
            float x3 = xr[(size_t)3 * Nn * 256];
            float emb = bb;
#pragma unroll
            for (int k = 0; k < 16; k++) emb = fmaf(s_attr[j][k], bw[k], emb);
            float v0 = x0 + emb, v1 = x1 + emb, v2 = x2 + emb, v3 = x3 + emb;
            acc0 += 0.5f * v0 * (1.0f + erff(v0 * 0.70710678118654752f)) * s_w[0][j];
            acc1 += 0.5f * v1 * (1.0f + erff(v1 * 0.70710678118654752f)) * s_w[1][j];
            acc2 += 0.5f * v2 * (1.0f + erff(v2 * 0.70710678118654752f)) * s_w[2][j];
            acc3 += 0.5f * v3 * (1.0f + erff(v3 * 0.70710678118654752f)) * s_w[3][j];
        }
    }

    float inv = 1.0f / (float)max(deg, 1);
    float vals[4] = {acc0 * inv, acc1 * inv, acc2 * inv, acc3 * inv};
    int kb = c >> 6, kc = c & 63;
#pragma unroll
    for (int rc = 0; rc < 4; rc++) {
        int m = rc * Nn + d;
        char* base = (char*)g_Asum + ((size_t)((m >> 7) * 4 + kb)) * 32768;
        uint32_t off = SWZ((uint32_t)((m & 127) * 128 + kc * 2));
        unsigned short hb, lb;
        split_bf16(vals[rc], hb, lb);
        *(unsigned short*)(base + off) = hb;
        *(unsigned short*)(base + 16384 + off) = lb;
    }
}

// ---------------------------------------------------------------------------
extern "C" void kernel_launch(void* const* d_in, const int* in_sizes, int n_in,
                              void* d_out, int out_size) {
    const float* x           = (const float*)d_in[0];
    const float* edge_attr   = (const float*)d_in[1];
    const float* edge_weight = (const float*)d_in[2];
    const float* lin_W       = (const float*)d_in[3];
    const float* lin_b       = (const float*)d_in[4];
    const float* linl_W      = (const float*)d_in[5];
    const float* linl_b      = (const float*)d_in[6];
    const float* linr_W      = (const float*)d_in[7];
    const float* bond_W      = (const float*)d_in[8];
    const float* bond_b      = (const float*)d_in[9];
    const int*   ei          = (const int*)d_in[10];
    float* out = (float*)d_out;

    const int SMEM_BYTES = 96 * 1024;
    cudaFuncSetAttribute(mm_gemm, cudaFuncAttributeMaxDynamicSharedMemorySize, SMEM_BYTES);

    zero_cnt<<<(Nn + 255) / 256, 256>>>();                       // 0
    conv_x<<<20000, 256>>>(x);                                   // 1
    prep_weights<<<768, 256>>>(lin_W, linl_W, linr_W);           // 2
    mm_gemm<<<dim3(2, 625), 256, SMEM_BYTES>>>(lin_b, nullptr, 4, 0);   // 3 <- profiled
    count_kernel<<<(Ee + 255) / 256, 256>>>(ei);                 // 4
    bsum_kernel<<<NB, 256>>>();                                  // 5
    bscan_kernel<<<1, 32>>>();                                   // 6
    seg_kernel<<<NB, 256>>>();                                   // 7
    scatter_kernel<<<(Ee + 255) / 256, 256>>>(ei);               // 8
    msg_sorted<<<Nn, 256>>>(edge_attr, edge_weight, bond_W, bond_b, ei); // 9
    mm_gemm<<<dim3(2, 625), 256, SMEM_BYTES>>>(linl_b, out, 8, 1);       // 10
}